// round 1
// baseline (speedup 1.0000x reference)
#include <cuda_runtime.h>
#include <cuda_bf16.h>

#define N_NODES 50000
#define IN_DIM 2000
#define GRAPH_DIM 512
#define HIDDEN_DIM 256
#define LATENT_DIM 64
#define N_EDGES 1600000
#define BN_EPS 1e-5f

// Scratch (device globals; allocation is forbidden)
__device__ float g_h[(size_t)N_NODES * GRAPH_DIM];     // x@Wg+bg, later reused as h0
__device__ float g_agg[(size_t)N_NODES * GRAPH_DIM];   // SpMM output
__device__ float g_h1[(size_t)N_NODES * HIDDEN_DIM];   // h0@W1+b1, then h1 (in place)
__device__ float g_stats0[2 * GRAPH_DIM];              // sum, sumsq
__device__ float g_stats1[2 * HIDDEN_DIM];

static inline int cdiv(int a, int b) { return (a + b - 1) / b; }

// ---------------------------------------------------------------------------
// Zero kernel (float4 grid-stride)
// ---------------------------------------------------------------------------
__global__ void zero_kernel(float4* __restrict__ p, long long n4) {
    long long i = (long long)blockIdx.x * blockDim.x + threadIdx.x;
    long long stride = (long long)gridDim.x * blockDim.x;
    float4 z = make_float4(0.f, 0.f, 0.f, 0.f);
    for (; i < n4; i += stride) p[i] = z;
}

// ---------------------------------------------------------------------------
// Tiled SGEMM: C[M,Nc] = A[M,K] @ B[K,Nc] + bias
// A row-major stride K, B row-major stride Nc, C row-major stride Nc.
// BK must divide K; BN must divide Nc; handles ragged M.
// ---------------------------------------------------------------------------
template <int BM, int BN, int BK, int TM, int TN>
__global__ void __launch_bounds__(256)
sgemm_bias(const float* __restrict__ A, const float* __restrict__ B,
           const float* __restrict__ bias, float* __restrict__ C,
           int M, int K, int Nc)
{
    constexpr int NT = (BM / TM) * (BN / TN);   // 256
    __shared__ float As[BK][BM + 4];
    __shared__ float Bs[BK][BN + 4];

    const int tid = threadIdx.x;
    const int tx = tid % (BN / TN);
    const int ty = tid / (BN / TN);
    const int rowBase = blockIdx.y * BM;
    const int colBase = blockIdx.x * BN;

    float acc[TM][TN];
#pragma unroll
    for (int i = 0; i < TM; i++)
#pragma unroll
        for (int j = 0; j < TN; j++) acc[i][j] = 0.f;

    constexpr int AK4 = BK / 4;
    constexpr int BN4 = BN / 4;

    for (int kt = 0; kt < K; kt += BK) {
        // Load A tile (BM x BK), transpose into As[k][m]
#pragma unroll
        for (int it = tid; it < BM * AK4; it += NT) {
            int r = it / AK4;
            int c4 = it % AK4;
            int gr = rowBase + r;
            float4 v = make_float4(0.f, 0.f, 0.f, 0.f);
            if (gr < M) v = *(const float4*)&A[(size_t)gr * K + kt + c4 * 4];
            As[c4 * 4 + 0][r] = v.x;
            As[c4 * 4 + 1][r] = v.y;
            As[c4 * 4 + 2][r] = v.z;
            As[c4 * 4 + 3][r] = v.w;
        }
        // Load B tile (BK x BN)
#pragma unroll
        for (int it = tid; it < BK * BN4; it += NT) {
            int r = it / BN4;
            int c4 = it % BN4;
            float4 v = *(const float4*)&B[(size_t)(kt + r) * Nc + colBase + c4 * 4];
            *(float4*)&Bs[r][c4 * 4] = v;
        }
        __syncthreads();

#pragma unroll
        for (int k = 0; k < BK; ++k) {
            float a[TM], b[TN];
#pragma unroll
            for (int i = 0; i < TM; i++) a[i] = As[k][ty * TM + i];
#pragma unroll
            for (int j = 0; j < TN; j++) b[j] = Bs[k][tx * TN + j];
#pragma unroll
            for (int i = 0; i < TM; i++)
#pragma unroll
                for (int j = 0; j < TN; j++) acc[i][j] += a[i] * b[j];
        }
        __syncthreads();
    }

    // Store + bias
#pragma unroll
    for (int i = 0; i < TM; i++) {
        int gr = rowBase + ty * TM + i;
        if (gr >= M) continue;
#pragma unroll
        for (int j = 0; j < TN; j += 4) {
            int gc = colBase + tx * TN + j;
            float4 v;
            v.x = acc[i][j + 0] + bias[gc + 0];
            v.y = acc[i][j + 1] + bias[gc + 1];
            v.z = acc[i][j + 2] + bias[gc + 2];
            v.w = acc[i][j + 3] + bias[gc + 3];
            *(float4*)&C[(size_t)gr * Nc + gc] = v;
        }
    }
}

// ---------------------------------------------------------------------------
// SpMM: agg[row] += val * h[col]  (edge-parallel, vec4 reduction, no return)
// Thread idx -> edge = idx>>7, feature-quad = idx&127. Coalesced 2KB rows.
// ---------------------------------------------------------------------------
__global__ void spmm_atomic(const int* __restrict__ rows, const int* __restrict__ cols,
                            const float* __restrict__ vals, const float* __restrict__ h,
                            float* __restrict__ agg)
{
    long long idx = (long long)blockIdx.x * blockDim.x + threadIdx.x;
    const long long total = (long long)N_EDGES * (GRAPH_DIM / 4);
    if (idx >= total) return;
    int e  = (int)(idx >> 7);   // GRAPH_DIM/4 = 128
    int f4 = (int)(idx & 127);
    int r = rows[e];
    int c = cols[e];
    float v = vals[e];
    float4 hv = *(const float4*)&h[(size_t)c * GRAPH_DIM + f4 * 4];
    float* dst = &agg[(size_t)r * GRAPH_DIM + f4 * 4];
    asm volatile("red.global.add.v4.f32 [%0], {%1, %2, %3, %4};"
                 :: "l"(dst), "f"(v * hv.x), "f"(v * hv.y), "f"(v * hv.z), "f"(v * hv.w)
                 : "memory");
}

// ---------------------------------------------------------------------------
// Column statistics: stats[0:C] += sum, stats[C:2C] += sumsq over row chunk
// ---------------------------------------------------------------------------
template <int C>
__global__ void colstats(const float* __restrict__ X, float* __restrict__ stats,
                         int Nrows, int rowsPerBlock)
{
    int col = blockIdx.x * blockDim.x + threadIdx.x;
    if (col >= C) return;
    int r0 = blockIdx.y * rowsPerBlock;
    int r1 = min(r0 + rowsPerBlock, Nrows);
    float s = 0.f, s2 = 0.f;
    for (int r = r0; r < r1; r++) {
        float v = X[(size_t)r * C + col];
        s += v;
        s2 += v * v;
    }
    atomicAdd(&stats[col], s);
    atomicAdd(&stats[C + col], s2);
}

// ---------------------------------------------------------------------------
// BatchNorm (training stats) + softplus, elementwise, vec4
// ---------------------------------------------------------------------------
__device__ __forceinline__ float softplus_f(float x) {
    return fmaxf(x, 0.f) + log1pf(expf(-fabsf(x)));
}

template <int C>
__global__ void bn_softplus(const float* __restrict__ X, const float* __restrict__ stats,
                            const float* __restrict__ gamma, const float* __restrict__ beta,
                            float* __restrict__ Y, int Nrows)
{
    long long i4 = (long long)blockIdx.x * blockDim.x + threadIdx.x;
    long long total4 = (long long)Nrows * C / 4;
    if (i4 >= total4) return;
    int col = (int)((i4 % (C / 4)) * 4);
    const float invN = 1.f / (float)Nrows;
    float4 x = ((const float4*)X)[i4];
    float4 y;
#pragma unroll
    for (int j = 0; j < 4; j++) {
        float xv = (&x.x)[j];
        int c = col + j;
        float mean = stats[c] * invN;
        float var = stats[C + c] * invN - mean * mean;
        float z = (xv - mean) * rsqrtf(var + BN_EPS) * gamma[c] + beta[c];
        (&y.x)[j] = softplus_f(z);
    }
    ((float4*)Y)[i4] = y;
}

// ---------------------------------------------------------------------------
// Launcher
// ---------------------------------------------------------------------------
extern "C" void kernel_launch(void* const* d_in, const int* in_sizes, int n_in,
                              void* d_out, int out_size)
{
    const float* x        = (const float*)d_in[0];
    const int*   adj_rows = (const int*)d_in[1];
    const int*   adj_cols = (const int*)d_in[2];
    const float* adj_vals = (const float*)d_in[3];
    const float* Wg  = (const float*)d_in[4];
    const float* bg  = (const float*)d_in[5];
    const float* W1  = (const float*)d_in[6];
    const float* b1  = (const float*)d_in[7];
    const float* W21 = (const float*)d_in[8];
    const float* b21 = (const float*)d_in[9];
    const float* W22 = (const float*)d_in[10];
    const float* b22 = (const float*)d_in[11];
    const float* gamma0 = (const float*)d_in[12];
    const float* beta0  = (const float*)d_in[13];
    const float* gamma1 = (const float*)d_in[14];
    const float* beta1  = (const float*)d_in[15];
    float* out = (float*)d_out;

    float *h, *agg, *h1, *st0, *st1;
    cudaGetSymbolAddress((void**)&h,   g_h);
    cudaGetSymbolAddress((void**)&agg, g_agg);
    cudaGetSymbolAddress((void**)&h1,  g_h1);
    cudaGetSymbolAddress((void**)&st0, g_stats0);
    cudaGetSymbolAddress((void**)&st1, g_stats1);

    // 0) zero agg + stats
    {
        long long n4 = (long long)N_NODES * GRAPH_DIM / 4;
        zero_kernel<<<4096, 256>>>((float4*)agg, n4);
        zero_kernel<<<1, 256>>>((float4*)st0, 2 * GRAPH_DIM / 4);
        zero_kernel<<<1, 256>>>((float4*)st1, 2 * HIDDEN_DIM / 4);
    }

    // 1) h = x @ Wg + bg     [50000,2000]x[2000,512]
    {
        dim3 grid(GRAPH_DIM / 128, cdiv(N_NODES, 128));
        sgemm_bias<128, 128, 16, 8, 8><<<grid, 256>>>(x, Wg, bg, h, N_NODES, IN_DIM, GRAPH_DIM);
    }

    // 2) SpMM: agg = segment_sum(vals * h[cols], rows)
    {
        long long total = (long long)N_EDGES * (GRAPH_DIM / 4);
        int blocks = (int)((total + 255) / 256);
        spmm_atomic<<<blocks, 256>>>(adj_rows, adj_cols, adj_vals, h, agg);
    }

    // 3) BN0 stats + normalize + softplus -> h (reuse as h0)
    {
        colstats<GRAPH_DIM><<<dim3(GRAPH_DIM / 256, cdiv(N_NODES, 512)), 256>>>(agg, st0, N_NODES, 512);
        long long total4 = (long long)N_NODES * GRAPH_DIM / 4;
        bn_softplus<GRAPH_DIM><<<(int)((total4 + 255) / 256), 256>>>(agg, st0, gamma0, beta0, h, N_NODES);
    }

    // 4) h1pre = h0 @ W1 + b1   [50000,512]x[512,256]
    {
        dim3 grid(HIDDEN_DIM / 128, cdiv(N_NODES, 128));
        sgemm_bias<128, 128, 16, 8, 8><<<grid, 256>>>(h, W1, b1, h1, N_NODES, GRAPH_DIM, HIDDEN_DIM);
    }

    // 5) BN1 + softplus in place
    {
        colstats<HIDDEN_DIM><<<dim3(1, cdiv(N_NODES, 512)), 256>>>(h1, st1, N_NODES, 512);
        long long total4 = (long long)N_NODES * HIDDEN_DIM / 4;
        bn_softplus<HIDDEN_DIM><<<(int)((total4 + 255) / 256), 256>>>(h1, st1, gamma1, beta1, h1, N_NODES);
    }

    // 6) mu = h1 @ W21 + b21 ; logvar = h1 @ W22 + b22   [50000,256]x[256,64]
    {
        dim3 grid(1, cdiv(N_NODES, 128));
        sgemm_bias<128, 64, 16, 8, 4><<<grid, 256>>>(h1, W21, b21, out, N_NODES, HIDDEN_DIM, LATENT_DIM);
        sgemm_bias<128, 64, 16, 8, 4><<<grid, 256>>>(h1, W22, b22, out + (size_t)N_NODES * LATENT_DIM,
                                                     N_NODES, HIDDEN_DIM, LATENT_DIM);
    }
    (void)in_sizes; (void)n_in; (void)out_size;
}

// round 3
// speedup vs baseline: 1.5131x; 1.5131x over previous
#include <cuda_runtime.h>
#include <cuda_bf16.h>
#include <cstdint>

#define N_NODES 50000
#define IN_DIM 2000
#define IN_DIM_PAD 2048
#define GRAPH_DIM 512
#define HIDDEN_DIM 256
#define LATENT_DIM 64
#define N_EDGES 1600000
#define BN_EPS 1e-5f

// Scratch (device globals; allocation is forbidden)
__device__ float g_h[(size_t)N_NODES * GRAPH_DIM];     // x@Wg+bg, later reused as h0
__device__ float g_agg[(size_t)N_NODES * GRAPH_DIM];   // SpMM output
__device__ float g_h1[(size_t)N_NODES * HIDDEN_DIM];   // h0@W1+b1, then h1 (in place)
__device__ float g_stats0[2 * GRAPH_DIM];
__device__ float g_stats1[2 * HIDDEN_DIM];
// Pre-transposed + bf16-split weights: [Nc][Kpad]
__device__ __nv_bfloat16 g_WgT_hi[(size_t)GRAPH_DIM * IN_DIM_PAD];
__device__ __nv_bfloat16 g_WgT_lo[(size_t)GRAPH_DIM * IN_DIM_PAD];
__device__ __nv_bfloat16 g_W1T_hi[(size_t)HIDDEN_DIM * GRAPH_DIM];
__device__ __nv_bfloat16 g_W1T_lo[(size_t)HIDDEN_DIM * GRAPH_DIM];
__device__ __nv_bfloat16 g_WlatT_hi[(size_t)128 * HIDDEN_DIM];
__device__ __nv_bfloat16 g_WlatT_lo[(size_t)128 * HIDDEN_DIM];
__device__ float g_blat[128];

static inline int cdiv(int a, int b) { return (a + b - 1) / b; }

// ---------------------------------------------------------------------------
// PTX helpers (arch-neutral: sm_80+ instructions only)
// ---------------------------------------------------------------------------
__device__ __forceinline__ uint32_t smem_u32(const void* p) {
    uint32_t a;
    asm("{ .reg .u64 t; cvta.to.shared.u64 t, %1; cvt.u32.u64 %0, t; }" : "=r"(a) : "l"(p));
    return a;
}
__device__ __forceinline__ void ldsm4(uint32_t* d, uint32_t addr) {
    asm volatile("ldmatrix.sync.aligned.m8n8.x4.shared.b16 {%0,%1,%2,%3}, [%4];"
                 : "=r"(d[0]), "=r"(d[1]), "=r"(d[2]), "=r"(d[3]) : "r"(addr));
}
__device__ __forceinline__ void mma_bf16(float* c, const uint32_t* a, const uint32_t* b) {
    asm volatile(
        "mma.sync.aligned.m16n8k16.row.col.f32.bf16.bf16.f32 "
        "{%0,%1,%2,%3}, {%4,%5,%6,%7}, {%8,%9}, {%0,%1,%2,%3};"
        : "+f"(c[0]), "+f"(c[1]), "+f"(c[2]), "+f"(c[3])
        : "r"(a[0]), "r"(a[1]), "r"(a[2]), "r"(a[3]), "r"(b[0]), "r"(b[1]));
}
__device__ __forceinline__ void cp16(uint32_t dst, const void* src) {
    asm volatile("cp.async.cg.shared.global [%0], [%1], 16;" :: "r"(dst), "l"(src));
}
#define CP_COMMIT() asm volatile("cp.async.commit_group;" ::: "memory")
#define CP_WAIT0()  asm volatile("cp.async.wait_group 0;" ::: "memory")

__device__ __forceinline__ uint32_t pack_bf16x2(__nv_bfloat16 lo, __nv_bfloat16 hi) {
    return ((uint32_t)__bfloat16_as_ushort(hi) << 16) | (uint32_t)__bfloat16_as_ushort(lo);
}

// ---------------------------------------------------------------------------
// Weight transpose + bf16 split:  W[K,Nc] fp32 -> Thi/Tlo [Nc][Kpad] bf16
// ---------------------------------------------------------------------------
__global__ void split_w_bf16(const float* __restrict__ W, __nv_bfloat16* __restrict__ Thi,
                             __nv_bfloat16* __restrict__ Tlo, int K, int Nc, int Kpad)
{
    int idx = blockIdx.x * blockDim.x + threadIdx.x;
    if (idx >= Nc * Kpad) return;
    int n = idx / Kpad;
    int k = idx % Kpad;
    float v = (k < K) ? W[(size_t)k * Nc + n] : 0.f;
    __nv_bfloat16 hi = __float2bfloat16(v);
    __nv_bfloat16 lo = __float2bfloat16(v - __bfloat162float(hi));
    Thi[idx] = hi;
    Tlo[idx] = lo;
}

__global__ void concat_bias(const float* __restrict__ b21, const float* __restrict__ b22,
                            float* __restrict__ blat)
{
    int t = threadIdx.x;
    if (t < 64) blat[t] = b21[t];
    else if (t < 128) blat[t] = b22[t - 64];
}

// ---------------------------------------------------------------------------
// bf16x3 tensor-core GEMM (mma.sync):  C[M,N] = A[M,Kvalid] @ Bsplit^T + bias
//   A fp32 row-major (lda = Kvalid); B pre-split bf16 [N][Kpad].
//   Tile 128x128xBK32, 256 threads (8 warps, 64x32 warptiles), double-buffered.
//   latent=1: N==128 and C is the mu||logvar split-store layout.
// ---------------------------------------------------------------------------
#define GBM 128
#define GBN 128
#define ROWB 80                 // padded smem row stride in bytes (32 bf16 -> 64B data)
#define TILEA (GBM * ROWB)      // 10240
#define STAGE_BYTES (4 * TILEA) // Ahi, Alo, Bhi, Blo
#define GSMEM (2 * STAGE_BYTES) // 81920

__global__ void __launch_bounds__(256)
bf16x3_gemm(const float* __restrict__ A, int lda, int Kvalid, int Kpad,
            const __nv_bfloat16* __restrict__ Bhi, const __nv_bfloat16* __restrict__ Blo,
            const float* __restrict__ bias, float* __restrict__ C, int ldc,
            int M, int latent)
{
    extern __shared__ char sm[];
    const uint32_t smb = smem_u32(sm);

    const int tid = threadIdx.x;
    const int lane = tid & 31;
    const int wid = tid >> 5;
    const int warpM = wid >> 2;     // 0..1
    const int warpN = wid & 3;      // 0..3
    const int rowBase = blockIdx.y * GBM;
    const int colBase = blockIdx.x * GBN;
    const int nIter = Kpad / 32;

    float acc[4][4][4];
#pragma unroll
    for (int i = 0; i < 4; i++)
#pragma unroll
        for (int j = 0; j < 4; j++)
#pragma unroll
            for (int v = 0; v < 4; v++) acc[i][j][v] = 0.f;

    // --- A loader state: 4 quads per thread ---
    float4 av[4];
    int arow[4], akq[4];
#pragma unroll
    for (int q = 0; q < 4; q++) {
        int qi = tid + q * 256;
        arow[q] = qi >> 3;
        akq[q] = qi & 7;
    }

    auto loadA = [&](int it) {
        int k0 = it * 32;
#pragma unroll
        for (int q = 0; q < 4; q++) {
            int gr = rowBase + arow[q];
            int k = k0 + akq[q] * 4;
            float4 v = make_float4(0.f, 0.f, 0.f, 0.f);
            if (gr < M) {
                const float* src = A + (size_t)gr * lda + k;
                if (k + 3 < Kvalid) {
                    v = *(const float4*)src;
                } else if (k < Kvalid) {
                    v.x = src[0];
                    if (k + 1 < Kvalid) v.y = src[1];
                    if (k + 2 < Kvalid) v.z = src[2];
                }
            }
            av[q] = v;
        }
    };

    auto stsA = [&](int stage) {
        char* sp = sm + stage * STAGE_BYTES;
#pragma unroll
        for (int q = 0; q < 4; q++) {
            float4 v = av[q];
            __nv_bfloat16 h0 = __float2bfloat16(v.x);
            __nv_bfloat16 h1 = __float2bfloat16(v.y);
            __nv_bfloat16 h2 = __float2bfloat16(v.z);
            __nv_bfloat16 h3 = __float2bfloat16(v.w);
            __nv_bfloat16 l0 = __float2bfloat16(v.x - __bfloat162float(h0));
            __nv_bfloat16 l1 = __float2bfloat16(v.y - __bfloat162float(h1));
            __nv_bfloat16 l2 = __float2bfloat16(v.z - __bfloat162float(h2));
            __nv_bfloat16 l3 = __float2bfloat16(v.w - __bfloat162float(h3));
            uint2 hp = make_uint2(pack_bf16x2(h0, h1), pack_bf16x2(h2, h3));
            uint2 lp = make_uint2(pack_bf16x2(l0, l1), pack_bf16x2(l2, l3));
            int off = arow[q] * ROWB + akq[q] * 8;
            *(uint2*)(sp + off) = hp;
            *(uint2*)(sp + TILEA + off) = lp;
        }
    };

    auto cpB = [&](int it, int stage) {
        int k0 = it * 32;
#pragma unroll
        for (int q = 0; q < 4; q++) {
            int ci = tid + q * 256;
            int hilo = ci >> 9;
            int row = (ci >> 2) & 127;
            int c = ci & 3;
            const __nv_bfloat16* src =
                (hilo ? Blo : Bhi) + (size_t)(colBase + row) * Kpad + k0 + c * 8;
            uint32_t dst = smb + stage * STAGE_BYTES + 2 * TILEA + hilo * TILEA
                           + row * ROWB + c * 16;
            cp16(dst, src);
        }
    };

    // ldmatrix per-lane base offsets
    const uint32_t aLaneOff = (uint32_t)((lane & 15) * ROWB + ((lane >> 4) << 4));
    const uint32_t bLaneOff = (uint32_t)(((lane & 7) + ((lane & 16) >> 1)) * ROWB
                                         + (((lane >> 3) & 1) << 4));

    // --- prologue ---
    loadA(0);
    cpB(0, 0);
    CP_COMMIT();
    stsA(0);

    for (int it = 0; it < nIter; ++it) {
        const int cur = it & 1;
        const int nxt = cur ^ 1;
        const bool more = (it + 1 < nIter);
        if (more) loadA(it + 1);
        CP_WAIT0();
        __syncthreads();
        if (more) {
            stsA(nxt);
            cpB(it + 1, nxt);
            CP_COMMIT();
        }

        // --- compute stage cur ---
        const uint32_t aBase = smb + cur * STAGE_BYTES + warpM * 64 * ROWB + aLaneOff;
        const uint32_t bBase = smb + cur * STAGE_BYTES + 2 * TILEA + warpN * 32 * ROWB + bLaneOff;
#pragma unroll
        for (int ks = 0; ks < 2; ks++) {
            const uint32_t kb = ks * 32;
            uint32_t bH[2][4], bL[2][4], aF[4][4];
            ldsm4(bH[0], bBase + kb);
            ldsm4(bH[1], bBase + 16 * ROWB + kb);
            ldsm4(bL[0], bBase + TILEA + kb);
            ldsm4(bL[1], bBase + TILEA + 16 * ROWB + kb);
#pragma unroll
            for (int mt = 0; mt < 4; mt++) ldsm4(aF[mt], aBase + mt * 16 * ROWB + kb);
#pragma unroll
            for (int mt = 0; mt < 4; mt++)
#pragma unroll
                for (int nt = 0; nt < 4; nt++)
                    mma_bf16(acc[mt][nt], aF[mt], &bH[nt >> 1][(nt & 1) * 2]);
#pragma unroll
            for (int mt = 0; mt < 4; mt++)
#pragma unroll
                for (int nt = 0; nt < 4; nt++)
                    mma_bf16(acc[mt][nt], aF[mt], &bL[nt >> 1][(nt & 1) * 2]);
#pragma unroll
            for (int mt = 0; mt < 4; mt++) ldsm4(aF[mt], aBase + TILEA + mt * 16 * ROWB + kb);
#pragma unroll
            for (int mt = 0; mt < 4; mt++)
#pragma unroll
                for (int nt = 0; nt < 4; nt++)
                    mma_bf16(acc[mt][nt], aF[mt], &bH[nt >> 1][(nt & 1) * 2]);
        }
    }

    // --- epilogue ---
    const int r0 = rowBase + warpM * 64 + (lane >> 2);
    const int c0 = colBase + warpN * 32 + (lane & 3) * 2;
#pragma unroll
    for (int mt = 0; mt < 4; mt++) {
#pragma unroll
        for (int nt = 0; nt < 4; nt++) {
            int r = r0 + mt * 16;
            int c = c0 + nt * 8;
            float b0 = bias[c], b1 = bias[c + 1];
            float v0 = acc[mt][nt][0] + b0;
            float v1 = acc[mt][nt][1] + b1;
            float v2 = acc[mt][nt][2] + b0;
            float v3 = acc[mt][nt][3] + b1;
            if (!latent) {
                if (r < M) *(float2*)&C[(size_t)r * ldc + c] = make_float2(v0, v1);
                if (r + 8 < M) *(float2*)&C[(size_t)(r + 8) * ldc + c] = make_float2(v2, v3);
            } else {
                float* base = (c < 64) ? C + c : C + (size_t)N_NODES * 64 + (c - 64);
                if (r < M) *(float2*)&base[(size_t)r * 64] = make_float2(v0, v1);
                if (r + 8 < M) *(float2*)&base[(size_t)(r + 8) * 64] = make_float2(v2, v3);
            }
        }
    }
}

// ---------------------------------------------------------------------------
// Zero kernel (float4 grid-stride)
// ---------------------------------------------------------------------------
__global__ void zero_kernel(float4* __restrict__ p, long long n4) {
    long long i = (long long)blockIdx.x * blockDim.x + threadIdx.x;
    long long stride = (long long)gridDim.x * blockDim.x;
    float4 z = make_float4(0.f, 0.f, 0.f, 0.f);
    for (; i < n4; i += stride) p[i] = z;
}

// ---------------------------------------------------------------------------
// SpMM: agg[row] += val * h[col]  (edge-parallel, vec4 reduction, no return)
// ---------------------------------------------------------------------------
__global__ void spmm_atomic(const int* __restrict__ rows, const int* __restrict__ cols,
                            const float* __restrict__ vals, const float* __restrict__ h,
                            float* __restrict__ agg)
{
    long long idx = (long long)blockIdx.x * blockDim.x + threadIdx.x;
    const long long total = (long long)N_EDGES * (GRAPH_DIM / 4);
    if (idx >= total) return;
    int e  = (int)(idx >> 7);
    int f4 = (int)(idx & 127);
    int r = rows[e];
    int c = cols[e];
    float v = vals[e];
    float4 hv = *(const float4*)&h[(size_t)c * GRAPH_DIM + f4 * 4];
    float* dst = &agg[(size_t)r * GRAPH_DIM + f4 * 4];
    asm volatile("red.global.add.v4.f32 [%0], {%1, %2, %3, %4};"
                 :: "l"(dst), "f"(v * hv.x), "f"(v * hv.y), "f"(v * hv.z), "f"(v * hv.w)
                 : "memory");
}

// ---------------------------------------------------------------------------
// Column statistics
// ---------------------------------------------------------------------------
template <int C>
__global__ void colstats(const float* __restrict__ X, float* __restrict__ stats,
                         int Nrows, int rowsPerBlock)
{
    int col = blockIdx.x * blockDim.x + threadIdx.x;
    if (col >= C) return;
    int r0 = blockIdx.y * rowsPerBlock;
    int r1 = min(r0 + rowsPerBlock, Nrows);
    float s = 0.f, s2 = 0.f;
    for (int r = r0; r < r1; r++) {
        float v = X[(size_t)r * C + col];
        s += v;
        s2 += v * v;
    }
    atomicAdd(&stats[col], s);
    atomicAdd(&stats[C + col], s2);
}

// ---------------------------------------------------------------------------
// BatchNorm + softplus
// ---------------------------------------------------------------------------
__device__ __forceinline__ float softplus_f(float x) {
    return fmaxf(x, 0.f) + log1pf(expf(-fabsf(x)));
}

template <int C>
__global__ void bn_softplus(const float* __restrict__ X, const float* __restrict__ stats,
                            const float* __restrict__ gamma, const float* __restrict__ beta,
                            float* __restrict__ Y, int Nrows)
{
    long long i4 = (long long)blockIdx.x * blockDim.x + threadIdx.x;
    long long total4 = (long long)Nrows * C / 4;
    if (i4 >= total4) return;
    int col = (int)((i4 % (C / 4)) * 4);
    const float invN = 1.f / (float)Nrows;
    float4 x = ((const float4*)X)[i4];
    float4 y;
#pragma unroll
    for (int j = 0; j < 4; j++) {
        float xv = (&x.x)[j];
        int c = col + j;
        float mean = stats[c] * invN;
        float var = stats[C + c] * invN - mean * mean;
        float z = (xv - mean) * rsqrtf(var + BN_EPS) * gamma[c] + beta[c];
        (&y.x)[j] = softplus_f(z);
    }
    ((float4*)Y)[i4] = y;
}

// ---------------------------------------------------------------------------
// Launcher
// ---------------------------------------------------------------------------
extern "C" void kernel_launch(void* const* d_in, const int* in_sizes, int n_in,
                              void* d_out, int out_size)
{
    const float* x        = (const float*)d_in[0];
    const int*   adj_rows = (const int*)d_in[1];
    const int*   adj_cols = (const int*)d_in[2];
    const float* adj_vals = (const float*)d_in[3];
    const float* Wg  = (const float*)d_in[4];
    const float* bg  = (const float*)d_in[5];
    const float* W1  = (const float*)d_in[6];
    const float* b1  = (const float*)d_in[7];
    const float* W21 = (const float*)d_in[8];
    const float* b21 = (const float*)d_in[9];
    const float* W22 = (const float*)d_in[10];
    const float* b22 = (const float*)d_in[11];
    const float* gamma0 = (const float*)d_in[12];
    const float* beta0  = (const float*)d_in[13];
    const float* gamma1 = (const float*)d_in[14];
    const float* beta1  = (const float*)d_in[15];
    float* out = (float*)d_out;

    float *h, *agg, *h1, *st0, *st1, *blat;
    __nv_bfloat16 *wgt_hi, *wgt_lo, *w1t_hi, *w1t_lo, *wlat_hi, *wlat_lo;
    cudaGetSymbolAddress((void**)&h,   g_h);
    cudaGetSymbolAddress((void**)&agg, g_agg);
    cudaGetSymbolAddress((void**)&h1,  g_h1);
    cudaGetSymbolAddress((void**)&st0, g_stats0);
    cudaGetSymbolAddress((void**)&st1, g_stats1);
    cudaGetSymbolAddress((void**)&blat, g_blat);
    cudaGetSymbolAddress((void**)&wgt_hi, g_WgT_hi);
    cudaGetSymbolAddress((void**)&wgt_lo, g_WgT_lo);
    cudaGetSymbolAddress((void**)&w1t_hi, g_W1T_hi);
    cudaGetSymbolAddress((void**)&w1t_lo, g_W1T_lo);
    cudaGetSymbolAddress((void**)&wlat_hi, g_WlatT_hi);
    cudaGetSymbolAddress((void**)&wlat_lo, g_WlatT_lo);

    cudaFuncSetAttribute(bf16x3_gemm, cudaFuncAttributeMaxDynamicSharedMemorySize, GSMEM);

    // 0) zero agg + stats; prep split weights & latent concat
    {
        long long n4 = (long long)N_NODES * GRAPH_DIM / 4;
        zero_kernel<<<4096, 256>>>((float4*)agg, n4);
        zero_kernel<<<1, 256>>>((float4*)st0, 2 * GRAPH_DIM / 4);
        zero_kernel<<<1, 256>>>((float4*)st1, 2 * HIDDEN_DIM / 4);
        int totWg = GRAPH_DIM * IN_DIM_PAD;
        split_w_bf16<<<cdiv(totWg, 256), 256>>>(Wg, wgt_hi, wgt_lo, IN_DIM, GRAPH_DIM, IN_DIM_PAD);
        int totW1 = HIDDEN_DIM * GRAPH_DIM;
        split_w_bf16<<<cdiv(totW1, 256), 256>>>(W1, w1t_hi, w1t_lo, GRAPH_DIM, HIDDEN_DIM, GRAPH_DIM);
        int totWl = 64 * HIDDEN_DIM;
        split_w_bf16<<<cdiv(totWl, 256), 256>>>(W21, wlat_hi, wlat_lo, HIDDEN_DIM, 64, HIDDEN_DIM);
        split_w_bf16<<<cdiv(totWl, 256), 256>>>(W22, wlat_hi + (size_t)64 * HIDDEN_DIM,
                                                wlat_lo + (size_t)64 * HIDDEN_DIM,
                                                HIDDEN_DIM, 64, HIDDEN_DIM);
        concat_bias<<<1, 128>>>(b21, b22, blat);
    }

    // 1) h = x @ Wg + bg   [50000,2000]x[2000,512]  (bf16x3 mma)
    {
        dim3 grid(GRAPH_DIM / GBN, cdiv(N_NODES, GBM));
        bf16x3_gemm<<<grid, 256, GSMEM>>>(x, IN_DIM, IN_DIM, IN_DIM_PAD,
                                          wgt_hi, wgt_lo, bg, h, GRAPH_DIM, N_NODES, 0);
    }

    // 2) SpMM
    {
        long long total = (long long)N_EDGES * (GRAPH_DIM / 4);
        int blocks = (int)((total + 255) / 256);
        spmm_atomic<<<blocks, 256>>>(adj_rows, adj_cols, adj_vals, h, agg);
    }

    // 3) BN0 + softplus -> h (reuse as h0)
    {
        colstats<GRAPH_DIM><<<dim3(GRAPH_DIM / 256, cdiv(N_NODES, 512)), 256>>>(agg, st0, N_NODES, 512);
        long long total4 = (long long)N_NODES * GRAPH_DIM / 4;
        bn_softplus<GRAPH_DIM><<<(int)((total4 + 255) / 256), 256>>>(agg, st0, gamma0, beta0, h, N_NODES);
    }

    // 4) h1pre = h0 @ W1 + b1   [50000,512]x[512,256]
    {
        dim3 grid(HIDDEN_DIM / GBN, cdiv(N_NODES, GBM));
        bf16x3_gemm<<<grid, 256, GSMEM>>>(h, GRAPH_DIM, GRAPH_DIM, GRAPH_DIM,
                                          w1t_hi, w1t_lo, b1, h1, HIDDEN_DIM, N_NODES, 0);
    }

    // 5) BN1 + softplus in place
    {
        colstats<HIDDEN_DIM><<<dim3(1, cdiv(N_NODES, 512)), 256>>>(h1, st1, N_NODES, 512);
        long long total4 = (long long)N_NODES * HIDDEN_DIM / 4;
        bn_softplus<HIDDEN_DIM><<<(int)((total4 + 255) / 256), 256>>>(h1, st1, gamma1, beta1, h1, N_NODES);
    }

    // 6) [mu | logvar] = h1 @ [W21|W22] + [b21|b22]  — one N=128 GEMM, split store
    {
        dim3 grid(1, cdiv(N_NODES, GBM));
        bf16x3_gemm<<<grid, 256, GSMEM>>>(h1, HIDDEN_DIM, HIDDEN_DIM, HIDDEN_DIM,
                                          wlat_hi, wlat_lo, blat, out, 0, N_NODES, 1);
    }
    (void)in_sizes; (void)n_in; (void)out_size;
}